// round 11
// baseline (speedup 1.0000x reference)
#include <cuda_runtime.h>
#include <cuda_fp16.h>
#include <math.h>
#include <stdint.h>

#define EPSY 0.1f
#define B_  64
#define P_  196
#define C_  768
#define TM_ 384
#define CM_ 3072
#define PPAD 224   // P_ padded to multiple of 32 halves (7 * 32)

// ---------------- scratch ----------------
__device__ __half g_xt16[(size_t)B_ * C_ * PPAD];
__device__ __half g_tw16[TM_ * PPAD];
__device__ __half g_w216[P_ * TM_];
__device__ __half g_cw16[(size_t)CM_ * C_];
__device__ __half g_w416[(size_t)C_ * CM_];
__device__ __half g_H116[(size_t)B_ * C_ * TM_];
__device__ float  g_X1[(size_t)B_ * P_ * C_];
__device__ __half g_X116[(size_t)B_ * P_ * C_];
__device__ __half g_H316[(size_t)B_ * P_ * CM_];
__device__ float g_twn[TM_];
__device__ float g_cwn[CM_];
__device__ float g_xn1[B_ * C_];
__device__ float g_xn2[B_ * P_];
__device__ float g_scales[2];

__device__ __forceinline__ unsigned smem_u32(const void* p) {
    return (unsigned)__cvta_generic_to_shared(p);
}
__device__ __forceinline__ void cp16(unsigned dst, const void* src, int bytes) {
    asm volatile("cp.async.ca.shared.global [%0], [%1], 16, %2;\n"
                 :: "r"(dst), "l"(src), "r"(bytes));
}
__device__ __forceinline__ void cp_commit() { asm volatile("cp.async.commit_group;\n"); }
__device__ __forceinline__ void cp_wait0() { asm volatile("cp.async.wait_group 0;\n"); }
__device__ __forceinline__ void cp_wait1() { asm volatile("cp.async.wait_group 1;\n"); }
__device__ __forceinline__ void cp_wait2() { asm volatile("cp.async.wait_group 2;\n"); }

__device__ __forceinline__ void ldsm4(unsigned& r0, unsigned& r1, unsigned& r2,
                                      unsigned& r3, uint32_t addr) {
    asm volatile("ldmatrix.sync.aligned.m8n8.x4.shared.b16 {%0,%1,%2,%3}, [%4];"
                 : "=r"(r0), "=r"(r1), "=r"(r2), "=r"(r3) : "r"(addr));
}

// ---------------- fused prep ----------------
__device__ __forceinline__ void cvt_dev(const float* __restrict__ in,
                                        __half* __restrict__ out,
                                        int R, int Kin, int Kout, int blk) {
    int idx = blk * 256 + threadIdx.x;
    int k8n = Kout >> 3;
    if (idx >= R * k8n) return;
    int r = idx / k8n, k8 = (idx % k8n) << 3;
    __half h[8];
    if (k8 + 8 <= Kin) {
        const float4* p = (const float4*)(in + (size_t)r * Kin + k8);
        float4 v0 = p[0], v1 = p[1];
        h[0] = __float2half_rn(v0.x); h[1] = __float2half_rn(v0.y);
        h[2] = __float2half_rn(v0.z); h[3] = __float2half_rn(v0.w);
        h[4] = __float2half_rn(v1.x); h[5] = __float2half_rn(v1.y);
        h[6] = __float2half_rn(v1.z); h[7] = __float2half_rn(v1.w);
    } else {
        #pragma unroll
        for (int j = 0; j < 8; j++)
            h[j] = (k8 + j < Kin) ? __float2half_rn(in[(size_t)r * Kin + k8 + j]) : __half(0.f);
    }
    uint4 u;
    u.x = *(unsigned*)&h[0]; u.y = *(unsigned*)&h[2];
    u.z = *(unsigned*)&h[4]; u.w = *(unsigned*)&h[6];
    *(uint4*)(out + (size_t)r * Kout + k8) = u;
}

__device__ __forceinline__ void rownorm_dev(const float* __restrict__ in,
                                            float* __restrict__ out,
                                            int M, int K, int blk) {
    int row = blk * 8 + (threadIdx.x >> 5);
    int lane = threadIdx.x & 31;
    if (row >= M) return;
    const float4* p = (const float4*)(in + (size_t)row * K);
    int n4 = K >> 2;
    float s = 0.f;
    for (int i = lane; i < n4; i += 32) {
        float4 v = p[i];
        s += v.x * v.x + v.y * v.y + v.z * v.z + v.w * v.w;
    }
    #pragma unroll
    for (int o = 16; o; o >>= 1) s += __shfl_xor_sync(0xffffffffu, s, o);
    if (lane == 0) out[row] = s;
}

// block ranges
#define NB_CW   1152   // cw  (3072 x 768)
#define NB_W4   1152   // w4  (768 x 3072)
#define NB_TW   42     // tw  (384 x 196 -> 224)
#define NB_W2   37     // w2  (196 x 384)
#define NB_RTW  48     // rownorm tw
#define NB_RCW  384    // rownorm cw
#define NB_Z    48     // zero xn1 + scales
#define NB_PREP (NB_CW + NB_W4 + NB_TW + NB_W2 + NB_RTW + NB_RCW + NB_Z)

__global__ void prep_mega(const float* __restrict__ tw, const float* __restrict__ w2,
                          const float* __restrict__ cw, const float* __restrict__ w4,
                          __half* __restrict__ tw16, __half* __restrict__ w216,
                          __half* __restrict__ cw16, __half* __restrict__ w416,
                          float* __restrict__ twn, float* __restrict__ cwn,
                          float* __restrict__ xn1,
                          const float* __restrict__ ta, const float* __restrict__ ca,
                          float* __restrict__ scl) {
    int b = blockIdx.x;
    if (b < NB_CW) { cvt_dev(cw, cw16, CM_, C_, C_, b); return; }
    b -= NB_CW;
    if (b < NB_W4) { cvt_dev(w4, w416, C_, CM_, CM_, b); return; }
    b -= NB_W4;
    if (b < NB_TW) { cvt_dev(tw, tw16, TM_, P_, PPAD, b); return; }
    b -= NB_TW;
    if (b < NB_W2) { cvt_dev(w2, w216, P_, TM_, TM_, b); return; }
    b -= NB_W2;
    if (b < NB_RTW) { rownorm_dev(tw, twn, TM_, P_, b); return; }
    b -= NB_RTW;
    if (b < NB_RCW) { rownorm_dev(cw, cwn, CM_, C_, b); return; }
    b -= NB_RCW;
    // zero xn1 + scales
    int i = b * 256 + threadIdx.x;
    if (i < B_ * C_ / 4) ((float4*)xn1)[i] = make_float4(0.f, 0.f, 0.f, 0.f);
    if (b == 0 && threadIdx.x == 0) {
        float bt = (float)((double)TM_ / log((double)TM_ + 1.0));
        float bc = (float)((double)CM_ / log((double)CM_ + 1.0));
        scl[0] = powf(sqrtf(bt), ta[0]);
        scl[1] = powf(sqrtf(bc), ca[0]);
    }
}

// transpose + convert + fused x-norm partials
__global__ void transpose_cvt_x(const float* __restrict__ x, __half* __restrict__ out,
                                float* __restrict__ xn1) {
    __shared__ float tile[32][33];
    const int b  = blockIdx.z;
    const int c0 = blockIdx.x * 32;
    const int p0 = blockIdx.y * 32;
    const int tx = threadIdx.x, ty = threadIdx.y;
    #pragma unroll
    for (int i = 0; i < 32; i += 8) {
        int p = p0 + ty + i;
        tile[ty + i][tx] = (p < P_) ? x[(size_t)b * P_ * C_ + (size_t)p * C_ + c0 + tx] : 0.f;
    }
    __syncthreads();
    const int tid = ty * 32 + tx;
    const int pl  = (tid & 15) * 2;
    const int ci  = tid >> 4;
    #pragma unroll
    for (int pass = 0; pass < 2; pass++) {
        int cl = pass * 16 + ci;
        __half2 v = __floats2half2_rn(tile[pl][cl], tile[pl + 1][cl]);
        *(__half2*)(out + ((size_t)b * C_ + c0 + cl) * PPAD + p0 + pl) = v;
    }
    if (tid < 32) {
        float s = 0.f;
        #pragma unroll 8
        for (int p = 0; p < 32; p++) { float v = tile[p][tid]; s += v * v; }
        atomicAdd(&xn1[(size_t)b * C_ + c0 + tid], s);
    }
}

// standalone rownorm (X1 between GEMM2 and GEMM3)
__global__ void rownorm_k(const float* __restrict__ in, float* __restrict__ out,
                          int M, int K) {
    rownorm_dev(in, out, M, K, blockIdx.x);
}

// ========== fp16 GEMM: 128x128 block, 32x64 warp tile, BK=64, ldmatrix ==========
#define EPI_YAT16 0
#define EPI_SCATD 1
#define EPI_RES32 2

__device__ __forceinline__ void mma_f16(float* c, const unsigned* a, const unsigned* b) {
    asm volatile(
        "mma.sync.aligned.m16n8k16.row.col.f32.f16.f16.f32 "
        "{%0,%1,%2,%3}, {%4,%5,%6,%7}, {%8,%9}, {%0,%1,%2,%3};\n"
        : "+f"(c[0]), "+f"(c[1]), "+f"(c[2]), "+f"(c[3])
        : "r"(a[0]), "r"(a[1]), "r"(a[2]), "r"(a[3]), "r"(b[0]), "r"(b[1]));
}

#define GSMEM_BYTES (3 * (128 * 128 + 128 * 128))   // 98304

template <int EPI>
__global__ __launch_bounds__(256, 2)
void gemm16c(const __half* __restrict__ A, int lda,
             const __half* __restrict__ Bw, int ldb, int NbValid,
             void* __restrict__ OutP, __half* __restrict__ Out16,
             int M, int N, int K, int kvalid, int ks_last,
             const float* __restrict__ bias,
             const float* __restrict__ wn, const float* __restrict__ xn,
             const float* __restrict__ scales, int scale_idx,
             const float* __restrict__ shortcut) {
    constexpr int BM = 128, BN = 128, BK = 64;
    constexpr int ABYTES = BM * 128, BBYTES = BN * 128, STAGE = ABYTES + BBYTES;
    extern __shared__ __align__(128) char smem[];
    const uint32_t sb = smem_u32(smem);

    const int t    = threadIdx.x;
    const int lane = t & 31;
    const int wid  = t >> 5;
    const int warp_m = wid & 3;
    const int warp_n = wid >> 2;
    const int g  = lane >> 2;
    const int tg = lane & 3;

    const int r0 = blockIdx.y * BM;
    const int n0 = blockIdx.x * BN;
    const int ntiles = K / BK;

    float acc[2][8][4];
    #pragma unroll
    for (int mt = 0; mt < 2; mt++)
        #pragma unroll
        for (int nt = 0; nt < 8; nt++)
            #pragma unroll
            for (int r = 0; r < 4; r++) acc[mt][nt][r] = 0.f;

    auto load_tile = [&](int i, int s) {
        const uint32_t Ab = sb + (uint32_t)s * STAGE;
        const uint32_t Bb = Ab + ABYTES;
        const int k0 = i * BK;
        #pragma unroll
        for (int j = 0; j < 4; j++) {
            int ch = t + j * 256;
            int r = ch >> 3, kq = ch & 7;
            int nb = (k0 + kq * 8 + 8 <= kvalid) ? 16 : 0;
            const __half* src = nb ? (A + (size_t)(r0 + r) * lda + k0 + kq * 8) : A;
            cp16(Ab + (uint32_t)(r * 128 + ((kq ^ (r & 7)) << 4)), src, nb);
        }
        #pragma unroll
        for (int j = 0; j < 4; j++) {
            int ch = t + j * 256;
            int r = ch >> 3, kq = ch & 7;
            int nb = (n0 + r < NbValid && k0 + kq * 8 + 8 <= kvalid) ? 16 : 0;
            const __half* src = nb ? (Bw + (size_t)(n0 + r) * ldb + k0 + kq * 8) : Bw;
            cp16(Bb + (uint32_t)(r * 128 + ((kq ^ (r & 7)) << 4)), src, nb);
        }
        cp_commit();
    };

    load_tile(0, 0); load_tile(1, 1); load_tile(2, 2);

    const int Lr  = lane & 7;
    const int hi8 = (lane >> 3) & 1;
    const int h   = lane >> 4;

    for (int i = 0; i < ntiles; i++) {
        int rem = ntiles - 1 - i; if (rem > 2) rem = 2;
        if (rem == 2) cp_wait2(); else if (rem == 1) cp_wait1(); else cp_wait0();
        __syncthreads();

        const uint32_t Ab = sb + (uint32_t)(i % 3) * STAGE;
        const uint32_t Bb = Ab + ABYTES;
        const int kmax = (i == ntiles - 1) ? ks_last : 4;
        #pragma unroll
        for (int ks = 0; ks < 4; ks++) {
            if (ks >= kmax) break;
            const uint32_t qoff = (uint32_t)(((2 * ks + h) ^ Lr) << 4);
            unsigned a[2][4];
            #pragma unroll
            for (int mt = 0; mt < 2; mt++) {
                uint32_t ad = Ab + (uint32_t)((warp_m * 32 + mt * 16 + Lr + hi8 * 8) * 128) + qoff;
                ldsm4(a[mt][0], a[mt][1], a[mt][2], a[mt][3], ad);
            }
            unsigned b[8][2];
            #pragma unroll
            for (int p = 0; p < 4; p++) {
                uint32_t bd = Bb + (uint32_t)((warp_n * 64 + p * 16 + Lr + hi8 * 8) * 128) + qoff;
                unsigned q0, q1, q2, q3;
                ldsm4(q0, q1, q2, q3, bd);
                b[2 * p][0] = q0; b[2 * p + 1][0] = q1;
                b[2 * p][1] = q2; b[2 * p + 1][1] = q3;
            }
            #pragma unroll
            for (int mt = 0; mt < 2; mt++)
                #pragma unroll
                for (int nt = 0; nt < 8; nt++)
                    mma_f16(acc[mt][nt], a[mt], b[nt]);
        }
        __syncthreads();
        if (i + 3 < ntiles) load_tile(i + 3, i % 3);
    }

    // ---- epilogue ----
    const float scale = (EPI == EPI_YAT16) ? scales[scale_idx] : 0.f;
    #pragma unroll
    for (int mt = 0; mt < 2; mt++) {
        #pragma unroll
        for (int half = 0; half < 2; half++) {
            const int row = r0 + warp_m * 32 + mt * 16 + g + half * 8;
            const float xnr = (EPI == EPI_YAT16) ? xn[row] : 0.f;
            #pragma unroll
            for (int nt = 0; nt < 8; nt++) {
                const int col = n0 + warp_n * 64 + nt * 8 + tg * 2;
                const float d0 = acc[mt][nt][half * 2 + 0];
                const float d1 = acc[mt][nt][half * 2 + 1];
                if (EPI == EPI_YAT16) {
                    float dot0 = d0 + bias[col];
                    float dot1 = d1 + bias[col + 1];
                    float v0 = scale * dot0 * dot0 / (wn[col]     + xnr - 2.f * d0 + EPSY);
                    float v1 = scale * dot1 * dot1 / (wn[col + 1] + xnr - 2.f * d1 + EPSY);
                    *(__half2*)(Out16 + (size_t)row * N + col) = __floats2half2_rn(v0, v1);
                } else if (EPI == EPI_RES32) {
                    float* Out = (float*)OutP;
                    size_t o = (size_t)row * N + col;
                    float2 v = make_float2(shortcut[o] + d0 + bias[col],
                                           shortcut[o + 1] + d1 + bias[col + 1]);
                    *(float2*)(Out + o) = v;
                } else { // EPI_SCATD: row = b*C + c
                    float* Out = (float*)OutP;
                    int b = row / C_, c = row % C_;
                    size_t base = (size_t)b * P_ * C_ + c;
                    if (col < N) {
                        size_t o = base + (size_t)col * C_;
                        float v = shortcut[o] + d0 + bias[col];
                        Out[o] = v;
                        Out16[((size_t)b * P_ + col) * C_ + c] = __float2half_rn(v);
                    }
                    if (col + 1 < N) {
                        size_t o = base + (size_t)(col + 1) * C_;
                        float v = shortcut[o] + d1 + bias[col + 1];
                        Out[o] = v;
                        Out16[((size_t)b * P_ + col + 1) * C_ + c] = __float2half_rn(v);
                    }
                }
            }
        }
    }
}

// ---------------- launch (single stream, serial) ----------------
extern "C" void kernel_launch(void* const* d_in, const int* in_sizes, int n_in,
                              void* d_out, int out_size) {
    const float* x  = (const float*)d_in[0];
    const float* tw = (const float*)d_in[1];
    const float* tb = (const float*)d_in[2];
    const float* ta = (const float*)d_in[3];
    const float* w2 = (const float*)d_in[4];
    const float* b2 = (const float*)d_in[5];
    const float* cw = (const float*)d_in[6];
    const float* cb = (const float*)d_in[7];
    const float* ca = (const float*)d_in[8];
    const float* w4 = (const float*)d_in[9];
    const float* b4 = (const float*)d_in[10];
    float* out = (float*)d_out;

    __half *xt16, *tw16, *w216, *cw16, *w416, *H116, *X116, *H316;
    float *X1, *twn, *cwn, *xn1, *xn2, *scl;
    cudaGetSymbolAddress((void**)&xt16, g_xt16);
    cudaGetSymbolAddress((void**)&tw16, g_tw16);
    cudaGetSymbolAddress((void**)&w216, g_w216);
    cudaGetSymbolAddress((void**)&cw16, g_cw16);
    cudaGetSymbolAddress((void**)&w416, g_w416);
    cudaGetSymbolAddress((void**)&H116, g_H116);
    cudaGetSymbolAddress((void**)&X1,   g_X1);
    cudaGetSymbolAddress((void**)&X116, g_X116);
    cudaGetSymbolAddress((void**)&H316, g_H316);
    cudaGetSymbolAddress((void**)&twn,  g_twn);
    cudaGetSymbolAddress((void**)&cwn,  g_cwn);
    cudaGetSymbolAddress((void**)&xn1,  g_xn1);
    cudaGetSymbolAddress((void**)&xn2,  g_xn2);
    cudaGetSymbolAddress((void**)&scl,  g_scales);

    static int once = 0;
    if (!once) {
        cudaFuncSetAttribute(gemm16c<EPI_YAT16>,
            cudaFuncAttributeMaxDynamicSharedMemorySize, GSMEM_BYTES);
        cudaFuncSetAttribute(gemm16c<EPI_SCATD>,
            cudaFuncAttributeMaxDynamicSharedMemorySize, GSMEM_BYTES);
        cudaFuncSetAttribute(gemm16c<EPI_RES32>,
            cudaFuncAttributeMaxDynamicSharedMemorySize, GSMEM_BYTES);
        once = 1;
    }

    const int M1 = B_ * C_;   // 49152
    const int M3 = B_ * P_;   // 12544

    // ---- prep: 1 fused kernel + transpose ----
    prep_mega<<<NB_PREP, 256>>>(tw, w2, cw, w4, tw16, w216, cw16, w416,
                                twn, cwn, xn1, ta, ca, scl);
    dim3 tb32(32, 8);
    transpose_cvt_x<<<dim3(C_ / 32, PPAD / 32, B_), tb32>>>(x, xt16, xn1);

    // GEMM1 + YAT (token): A=xt16 (M1 x 224), B=tw16 (384 x 224); K=256, kvalid=224
    gemm16c<EPI_YAT16><<<dim3(TM_ / 128, M1 / 128), 256, GSMEM_BYTES>>>(
        xt16, PPAD, tw16, PPAD, TM_, nullptr, H116,
        M1, TM_, 256, PPAD, 2, tb, twn, xn1, scl, 0, nullptr);

    // GEMM2 + residual scatter -> X1 fp32 + X116 fp16 (K=384)
    gemm16c<EPI_SCATD><<<dim3(2, M1 / 128), 256, GSMEM_BYTES>>>(
        H116, TM_, w216, TM_, P_, X1, X116,
        M1, P_, TM_, TM_, 4, b2, nullptr, nullptr, nullptr, 0, x);

    rownorm_k<<<(M3 + 7) / 8, 256>>>(X1, xn2, M3, C_);

    // GEMM3 + YAT (channel): K=768
    gemm16c<EPI_YAT16><<<dim3(CM_ / 128, M3 / 128), 256, GSMEM_BYTES>>>(
        X116, C_, cw16, C_, CM_, nullptr, H316,
        M3, CM_, C_, C_, 4, cb, cwn, xn2, scl, 1, nullptr);

    // GEMM4 + residual: K=3072
    gemm16c<EPI_RES32><<<dim3(C_ / 128, M3 / 128), 256, GSMEM_BYTES>>>(
        H316, CM_, w416, CM_, C_, out, nullptr,
        M3, C_, CM_, CM_, 4, b4, nullptr, nullptr, nullptr, 0, X1);
}

// round 12
// speedup vs baseline: 1.1127x; 1.1127x over previous
#include <cuda_runtime.h>
#include <cuda_fp16.h>
#include <math.h>
#include <stdint.h>

#define EPSY 0.1f
#define B_  64
#define P_  196
#define C_  768
#define TM_ 384
#define CM_ 3072
#define PPAD 256   // P_ padded to multiple of 64 halves
#define P2PAD 256  // w2 rows padded for GEMM2 A-operand

// ---------------- scratch ----------------
__device__ __half g_xt16[(size_t)B_ * C_ * PPAD];
__device__ __half g_tw16[TM_ * PPAD];
__device__ __half g_w216[P2PAD * TM_];                 // padded rows; 196 valid
__device__ __half g_cw16[(size_t)CM_ * C_];
__device__ __half g_w416[(size_t)C_ * CM_];
__device__ __half g_H116[(size_t)B_ * C_ * TM_];
__device__ float  g_X1[(size_t)B_ * P_ * C_];
__device__ __half g_X116[(size_t)B_ * P_ * C_];
__device__ __half g_H316[(size_t)B_ * P_ * CM_];
__device__ float g_twn[TM_];
__device__ float g_cwn[CM_];
__device__ float g_xn1[B_ * C_];
__device__ float g_xn2[B_ * P_];
__device__ float g_scales[2];

__device__ __forceinline__ unsigned smem_u32(const void* p) {
    return (unsigned)__cvta_generic_to_shared(p);
}
__device__ __forceinline__ void cp16(unsigned dst, const void* src, int bytes) {
    asm volatile("cp.async.ca.shared.global [%0], [%1], 16, %2;\n"
                 :: "r"(dst), "l"(src), "r"(bytes));
}
__device__ __forceinline__ void cp_commit() { asm volatile("cp.async.commit_group;\n"); }
__device__ __forceinline__ void cp_wait0() { asm volatile("cp.async.wait_group 0;\n"); }
__device__ __forceinline__ void cp_wait1() { asm volatile("cp.async.wait_group 1;\n"); }
__device__ __forceinline__ void cp_wait2() { asm volatile("cp.async.wait_group 2;\n"); }

__device__ __forceinline__ void ldsm4(unsigned& r0, unsigned& r1, unsigned& r2,
                                      unsigned& r3, uint32_t addr) {
    asm volatile("ldmatrix.sync.aligned.m8n8.x4.shared.b16 {%0,%1,%2,%3}, [%4];"
                 : "=r"(r0), "=r"(r1), "=r"(r2), "=r"(r3) : "r"(addr));
}

// ---------------- fused prep ----------------
__device__ __forceinline__ void cvt_dev(const float* __restrict__ in,
                                        __half* __restrict__ out,
                                        int R, int Kin, int Kout, int blk) {
    int idx = blk * 256 + threadIdx.x;
    int k8n = Kout >> 3;
    if (idx >= R * k8n) return;
    int r = idx / k8n, k8 = (idx % k8n) << 3;
    __half h[8];
    if (k8 + 8 <= Kin) {
        const float4* p = (const float4*)(in + (size_t)r * Kin + k8);
        float4 v0 = p[0], v1 = p[1];
        h[0] = __float2half_rn(v0.x); h[1] = __float2half_rn(v0.y);
        h[2] = __float2half_rn(v0.z); h[3] = __float2half_rn(v0.w);
        h[4] = __float2half_rn(v1.x); h[5] = __float2half_rn(v1.y);
        h[6] = __float2half_rn(v1.z); h[7] = __float2half_rn(v1.w);
    } else {
        #pragma unroll
        for (int j = 0; j < 8; j++)
            h[j] = (k8 + j < Kin) ? __float2half_rn(in[(size_t)r * Kin + k8 + j]) : __half(0.f);
    }
    uint4 u;
    u.x = *(unsigned*)&h[0]; u.y = *(unsigned*)&h[2];
    u.z = *(unsigned*)&h[4]; u.w = *(unsigned*)&h[6];
    *(uint4*)(out + (size_t)r * Kout + k8) = u;
}

__device__ __forceinline__ void rownorm_dev(const float* __restrict__ in,
                                            float* __restrict__ out,
                                            int M, int K, int blk) {
    int row = blk * 8 + (threadIdx.x >> 5);
    int lane = threadIdx.x & 31;
    if (row >= M) return;
    const float4* p = (const float4*)(in + (size_t)row * K);
    int n4 = K >> 2;
    float s = 0.f;
    for (int i = lane; i < n4; i += 32) {
        float4 v = p[i];
        s += v.x * v.x + v.y * v.y + v.z * v.z + v.w * v.w;
    }
    #pragma unroll
    for (int o = 16; o; o >>= 1) s += __shfl_xor_sync(0xffffffffu, s, o);
    if (lane == 0) out[row] = s;
}

// block ranges
#define NB_CW   1152   // cw  (3072 x 768)
#define NB_W4   1152   // w4  (768 x 3072)
#define NB_TW   48     // tw  (384 x 196 -> 256)
#define NB_W2   37     // w2  (196 x 384)
#define NB_RTW  48     // rownorm tw
#define NB_RCW  384    // rownorm cw
#define NB_Z    48     // zero xn1 + scales
#define NB_PREP (NB_CW + NB_W4 + NB_TW + NB_W2 + NB_RTW + NB_RCW + NB_Z)

__global__ void prep_mega(const float* __restrict__ tw, const float* __restrict__ w2,
                          const float* __restrict__ cw, const float* __restrict__ w4,
                          __half* __restrict__ tw16, __half* __restrict__ w216,
                          __half* __restrict__ cw16, __half* __restrict__ w416,
                          float* __restrict__ twn, float* __restrict__ cwn,
                          float* __restrict__ xn1,
                          const float* __restrict__ ta, const float* __restrict__ ca,
                          float* __restrict__ scl) {
    int b = blockIdx.x;
    if (b < NB_CW) { cvt_dev(cw, cw16, CM_, C_, C_, b); return; }
    b -= NB_CW;
    if (b < NB_W4) { cvt_dev(w4, w416, C_, CM_, CM_, b); return; }
    b -= NB_W4;
    if (b < NB_TW) { cvt_dev(tw, tw16, TM_, P_, PPAD, b); return; }
    b -= NB_TW;
    if (b < NB_W2) { cvt_dev(w2, w216, P_, TM_, TM_, b); return; }
    b -= NB_W2;
    if (b < NB_RTW) { rownorm_dev(tw, twn, TM_, P_, b); return; }
    b -= NB_RTW;
    if (b < NB_RCW) { rownorm_dev(cw, cwn, CM_, C_, b); return; }
    b -= NB_RCW;
    int i = b * 256 + threadIdx.x;
    if (i < B_ * C_ / 4) ((float4*)xn1)[i] = make_float4(0.f, 0.f, 0.f, 0.f);
    if (b == 0 && threadIdx.x == 0) {
        float bt = (float)((double)TM_ / log((double)TM_ + 1.0));
        float bc = (float)((double)CM_ / log((double)CM_ + 1.0));
        scl[0] = powf(sqrtf(bt), ta[0]);
        scl[1] = powf(sqrtf(bc), ca[0]);
    }
}

// transpose + convert + fused x-norm partials
__global__ void transpose_cvt_x(const float* __restrict__ x, __half* __restrict__ out,
                                float* __restrict__ xn1) {
    __shared__ float tile[32][33];
    const int b  = blockIdx.z;
    const int c0 = blockIdx.x * 32;
    const int p0 = blockIdx.y * 32;
    const int tx = threadIdx.x, ty = threadIdx.y;
    #pragma unroll
    for (int i = 0; i < 32; i += 8) {
        int p = p0 + ty + i;
        tile[ty + i][tx] = (p < P_) ? x[(size_t)b * P_ * C_ + (size_t)p * C_ + c0 + tx] : 0.f;
    }
    __syncthreads();
    const int tid = ty * 32 + tx;
    const int pl  = (tid & 15) * 2;
    const int ci  = tid >> 4;
    #pragma unroll
    for (int pass = 0; pass < 2; pass++) {
        int cl = pass * 16 + ci;
        __half2 v = __floats2half2_rn(tile[pl][cl], tile[pl + 1][cl]);
        *(__half2*)(out + ((size_t)b * C_ + c0 + cl) * PPAD + p0 + pl) = v;
    }
    if (tid < 32) {
        float s = 0.f;
        #pragma unroll 8
        for (int p = 0; p < 32; p++) { float v = tile[p][tid]; s += v * v; }
        atomicAdd(&xn1[(size_t)b * C_ + c0 + tid], s);
    }
}

__global__ void rownorm_k(const float* __restrict__ in, float* __restrict__ out,
                          int M, int K) {
    rownorm_dev(in, out, M, K, blockIdx.x);
}

// ========== fp16 GEMM: 128x128 block, 32x64 warp tile, BK=64, ldmatrix ==========
#define EPI_YAT16 0
#define EPI_RESD  1
#define EPI_RES32 2

__device__ __forceinline__ void mma_f16(float* c, const unsigned* a, const unsigned* b) {
    asm volatile(
        "mma.sync.aligned.m16n8k16.row.col.f32.f16.f16.f32 "
        "{%0,%1,%2,%3}, {%4,%5,%6,%7}, {%8,%9}, {%0,%1,%2,%3};\n"
        : "+f"(c[0]), "+f"(c[1]), "+f"(c[2]), "+f"(c[3])
        : "r"(a[0]), "r"(a[1]), "r"(a[2]), "r"(a[3]), "r"(b[0]), "r"(b[1]));
}

#define GSMEM_BYTES (3 * (128 * 128 + 128 * 128))   // 98304

template <int EPI>
__global__ __launch_bounds__(256, 2)
void gemm16c(const __half* __restrict__ A, int lda,
             const __half* __restrict__ Bw, int ldb, int NbValid,
             void* __restrict__ OutP, __half* __restrict__ Out16,
             int M, int N, int K, int Mvalid,
             size_t zB, size_t zO,
             const float* __restrict__ bias,
             const float* __restrict__ wn, const float* __restrict__ xn,
             const float* __restrict__ scales, int scale_idx,
             const float* __restrict__ shortcut) {
    constexpr int BM = 128, BN = 128, BK = 64;
    constexpr int ABYTES = BM * 128, BBYTES = BN * 128, STAGE = ABYTES + BBYTES;
    extern __shared__ __align__(128) char smem[];
    const uint32_t sb = smem_u32(smem);

    const int t    = threadIdx.x;
    const int lane = t & 31;
    const int wid  = t >> 5;
    const int warp_m = wid & 3;
    const int warp_n = wid >> 2;
    const int g  = lane >> 2;
    const int tg = lane & 3;

    const size_t zz = blockIdx.z;
    const __half* Bz = Bw + zz * zB;

    const int r0 = blockIdx.y * BM;
    const int n0 = blockIdx.x * BN;
    const int ntiles = K / BK;

    float acc[2][8][4];
    #pragma unroll
    for (int mt = 0; mt < 2; mt++)
        #pragma unroll
        for (int nt = 0; nt < 8; nt++)
            #pragma unroll
            for (int r = 0; r < 4; r++) acc[mt][nt][r] = 0.f;

    auto load_tile = [&](int i, int s) {
        const uint32_t Ab = sb + (uint32_t)s * STAGE;
        const uint32_t Bb = Ab + ABYTES;
        const int k0 = i * BK;
        #pragma unroll
        for (int j = 0; j < 4; j++) {
            int ch = t + j * 256;
            int r = ch >> 3, kq = ch & 7;
            cp16(Ab + (uint32_t)(r * 128 + ((kq ^ (r & 7)) << 4)),
                 A + (size_t)(r0 + r) * lda + k0 + kq * 8, 16);
        }
        #pragma unroll
        for (int j = 0; j < 4; j++) {
            int ch = t + j * 256;
            int r = ch >> 3, kq = ch & 7;
            int nb = (n0 + r < NbValid) ? 16 : 0;
            const __half* src = nb ? (Bz + (size_t)(n0 + r) * ldb + k0 + kq * 8) : Bz;
            cp16(Bb + (uint32_t)(r * 128 + ((kq ^ (r & 7)) << 4)), src, nb);
        }
        cp_commit();
    };

    load_tile(0, 0); load_tile(1, 1); load_tile(2, 2);

    const int Lr  = lane & 7;
    const int hi8 = (lane >> 3) & 1;
    const int h   = lane >> 4;

    for (int i = 0; i < ntiles; i++) {
        int rem = ntiles - 1 - i; if (rem > 2) rem = 2;
        if (rem == 2) cp_wait2(); else if (rem == 1) cp_wait1(); else cp_wait0();
        __syncthreads();

        const uint32_t Ab = sb + (uint32_t)(i % 3) * STAGE;
        const uint32_t Bb = Ab + ABYTES;
        #pragma unroll
        for (int ks = 0; ks < 4; ks++) {
            const uint32_t qoff = (uint32_t)(((2 * ks + h) ^ Lr) << 4);
            unsigned a[2][4];
            #pragma unroll
            for (int mt = 0; mt < 2; mt++) {
                uint32_t ad = Ab + (uint32_t)((warp_m * 32 + mt * 16 + Lr + hi8 * 8) * 128) + qoff;
                ldsm4(a[mt][0], a[mt][1], a[mt][2], a[mt][3], ad);
            }
            unsigned b[8][2];
            #pragma unroll
            for (int p = 0; p < 4; p++) {
                uint32_t bd = Bb + (uint32_t)((warp_n * 64 + p * 16 + Lr + hi8 * 8) * 128) + qoff;
                unsigned q0, q1, q2, q3;
                ldsm4(q0, q1, q2, q3, bd);
                b[2 * p][0] = q0; b[2 * p + 1][0] = q1;
                b[2 * p][1] = q2; b[2 * p + 1][1] = q3;
            }
            #pragma unroll
            for (int mt = 0; mt < 2; mt++)
                #pragma unroll
                for (int nt = 0; nt < 8; nt++)
                    mma_f16(acc[mt][nt], a[mt], b[nt]);
        }
        __syncthreads();
        if (i + 3 < ntiles) load_tile(i + 3, i % 3);
    }

    // ---- epilogue ----
    const float scale = (EPI == EPI_YAT16) ? scales[scale_idx] : 0.f;
    #pragma unroll
    for (int mt = 0; mt < 2; mt++) {
        #pragma unroll
        for (int half = 0; half < 2; half++) {
            const int row = r0 + warp_m * 32 + mt * 16 + g + half * 8;
            if (EPI == EPI_RESD && row >= Mvalid) continue;
            const float xnr = (EPI == EPI_YAT16) ? xn[row] : 0.f;
            const float br  = (EPI == EPI_RESD) ? bias[row] : 0.f;
            #pragma unroll
            for (int nt = 0; nt < 8; nt++) {
                const int col = n0 + warp_n * 64 + nt * 8 + tg * 2;
                const float d0 = acc[mt][nt][half * 2 + 0];
                const float d1 = acc[mt][nt][half * 2 + 1];
                if (EPI == EPI_YAT16) {
                    float dot0 = d0 + bias[col];
                    float dot1 = d1 + bias[col + 1];
                    float v0 = scale * dot0 * dot0 / (wn[col]     + xnr - 2.f * d0 + EPSY);
                    float v1 = scale * dot1 * dot1 / (wn[col + 1] + xnr - 2.f * d1 + EPSY);
                    *(__half2*)(Out16 + (size_t)row * N + col) = __floats2half2_rn(v0, v1);
                } else if (EPI == EPI_RES32) {
                    float* Out = (float*)OutP;
                    size_t o = (size_t)row * N + col;
                    float2 v = make_float2(shortcut[o] + d0 + bias[col],
                                           shortcut[o + 1] + d1 + bias[col + 1]);
                    *(float2*)(Out + o) = v;
                } else { // EPI_RESD: batched, coalesced dual write (fp32 + fp16)
                    float* Out = (float*)OutP;
                    size_t o = zz * zO + (size_t)row * N + col;
                    float v0 = shortcut[o]     + d0 + br;
                    float v1 = shortcut[o + 1] + d1 + br;
                    *(float2*)(Out + o) = make_float2(v0, v1);
                    *(__half2*)(Out16 + o) = __floats2half2_rn(v0, v1);
                }
            }
        }
    }
}

// ---------------- launch (single stream, serial) ----------------
extern "C" void kernel_launch(void* const* d_in, const int* in_sizes, int n_in,
                              void* d_out, int out_size) {
    const float* x  = (const float*)d_in[0];
    const float* tw = (const float*)d_in[1];
    const float* tb = (const float*)d_in[2];
    const float* ta = (const float*)d_in[3];
    const float* w2 = (const float*)d_in[4];
    const float* b2 = (const float*)d_in[5];
    const float* cw = (const float*)d_in[6];
    const float* cb = (const float*)d_in[7];
    const float* ca = (const float*)d_in[8];
    const float* w4 = (const float*)d_in[9];
    const float* b4 = (const float*)d_in[10];
    float* out = (float*)d_out;

    __half *xt16, *tw16, *w216, *cw16, *w416, *H116, *X116, *H316;
    float *X1, *twn, *cwn, *xn1, *xn2, *scl;
    cudaGetSymbolAddress((void**)&xt16, g_xt16);
    cudaGetSymbolAddress((void**)&tw16, g_tw16);
    cudaGetSymbolAddress((void**)&w216, g_w216);
    cudaGetSymbolAddress((void**)&cw16, g_cw16);
    cudaGetSymbolAddress((void**)&w416, g_w416);
    cudaGetSymbolAddress((void**)&H116, g_H116);
    cudaGetSymbolAddress((void**)&X1,   g_X1);
    cudaGetSymbolAddress((void**)&X116, g_X116);
    cudaGetSymbolAddress((void**)&H316, g_H316);
    cudaGetSymbolAddress((void**)&twn,  g_twn);
    cudaGetSymbolAddress((void**)&cwn,  g_cwn);
    cudaGetSymbolAddress((void**)&xn1,  g_xn1);
    cudaGetSymbolAddress((void**)&xn2,  g_xn2);
    cudaGetSymbolAddress((void**)&scl,  g_scales);

    static int once = 0;
    if (!once) {
        cudaFuncSetAttribute(gemm16c<EPI_YAT16>,
            cudaFuncAttributeMaxDynamicSharedMemorySize, GSMEM_BYTES);
        cudaFuncSetAttribute(gemm16c<EPI_RESD>,
            cudaFuncAttributeMaxDynamicSharedMemorySize, GSMEM_BYTES);
        cudaFuncSetAttribute(gemm16c<EPI_RES32>,
            cudaFuncAttributeMaxDynamicSharedMemorySize, GSMEM_BYTES);
        once = 1;
    }

    const int M1 = B_ * C_;   // 49152
    const int M3 = B_ * P_;   // 12544

    // ---- prep: 1 fused kernel + transpose ----
    prep_mega<<<NB_PREP, 256>>>(tw, w2, cw, w4, tw16, w216, cw16, w416,
                                twn, cwn, xn1, ta, ca, scl);
    dim3 tb32(32, 8);
    transpose_cvt_x<<<dim3(C_ / 32, PPAD / 32, B_), tb32>>>(x, xt16, xn1);

    // GEMM1 + YAT (token): A=xt16 (M1 x 256), B=tw16 (384 x 256) -> H116 fp16
    gemm16c<EPI_YAT16><<<dim3(TM_ / 128, M1 / 128, 1), 256, GSMEM_BYTES>>>(
        xt16, PPAD, tw16, PPAD, TM_, nullptr, H116,
        M1, TM_, PPAD, M1, 0, 0, tb, twn, xn1, scl, 0, nullptr);

    // GEMM2 (batched over b): X1[b,p,c] = sum_t w2[p,t] * H1[(b,c),t] + x + b2[p]
    // A = w216 (256-pad x 384), B = H116 batch slice (768 x 384), coalesced output
    gemm16c<EPI_RESD><<<dim3(C_ / 128, 2, B_), 256, GSMEM_BYTES>>>(
        w216, TM_, H116, TM_, C_, X1, X116,
        P2PAD, C_, TM_, P_, (size_t)C_ * TM_, (size_t)P_ * C_,
        b2, nullptr, nullptr, nullptr, 0, x);

    rownorm_k<<<(M3 + 7) / 8, 256>>>(X1, xn2, M3, C_);

    // GEMM3 + YAT (channel): A=X116 (M3 x 768), B=cw16 (3072 x 768) -> H316 fp16
    gemm16c<EPI_YAT16><<<dim3(CM_ / 128, M3 / 128, 1), 256, GSMEM_BYTES>>>(
        X116, C_, cw16, C_, CM_, nullptr, H316,
        M3, CM_, C_, M3, 0, 0, cb, cwn, xn2, scl, 1, nullptr);

    // GEMM4 + residual: A=H316 (M3 x 3072), B=w416 (768 x 3072) -> out fp32
    gemm16c<EPI_RES32><<<dim3(C_ / 128, M3 / 128, 1), 256, GSMEM_BYTES>>>(
        H316, CM_, w416, CM_, C_, out, nullptr,
        M3, C_, CM_, M3, 0, 0, b4, nullptr, nullptr, nullptr, 0, X1);
}

// round 14
// speedup vs baseline: 1.1336x; 1.0187x over previous
#include <cuda_runtime.h>
#include <cuda_fp16.h>
#include <math.h>
#include <stdint.h>

#define EPSY 0.1f
#define B_  64
#define P_  196
#define C_  768
#define TM_ 384
#define CM_ 3072
#define PPAD 256   // P_ padded to multiple of 64 halves
#define P2PAD 256  // w2 rows padded for GEMM2 A-operand

// ---------------- scratch ----------------
__device__ __half g_xt16[(size_t)B_ * C_ * PPAD];
__device__ __half g_tw16[TM_ * PPAD];
__device__ __half g_w216[P2PAD * TM_];                 // padded rows; 196 valid
__device__ __half g_cw16[(size_t)CM_ * C_];
__device__ __half g_w416[(size_t)C_ * CM_];
__device__ __half g_H116[(size_t)B_ * C_ * TM_];
__device__ float  g_X1[(size_t)B_ * P_ * C_];
__device__ __half g_X116[(size_t)B_ * P_ * C_];
__device__ __half g_H316[(size_t)B_ * P_ * CM_];
__device__ float g_twn[TM_];
__device__ float g_cwn[CM_];
__device__ float g_xn1[B_ * C_];
__device__ float g_xn2[B_ * P_];
__device__ float g_scales[2];

__device__ __forceinline__ unsigned smem_u32(const void* p) {
    return (unsigned)__cvta_generic_to_shared(p);
}
__device__ __forceinline__ void cp16(unsigned dst, const void* src, int bytes) {
    asm volatile("cp.async.ca.shared.global [%0], [%1], 16, %2;\n"
                 :: "r"(dst), "l"(src), "r"(bytes));
}
__device__ __forceinline__ void cp_commit() { asm volatile("cp.async.commit_group;\n"); }
__device__ __forceinline__ void cp_wait0() { asm volatile("cp.async.wait_group 0;\n"); }
__device__ __forceinline__ void cp_wait1() { asm volatile("cp.async.wait_group 1;\n"); }
__device__ __forceinline__ void cp_wait2() { asm volatile("cp.async.wait_group 2;\n"); }

__device__ __forceinline__ void ldsm4(unsigned& r0, unsigned& r1, unsigned& r2,
                                      unsigned& r3, uint32_t addr) {
    asm volatile("ldmatrix.sync.aligned.m8n8.x4.shared.b16 {%0,%1,%2,%3}, [%4];"
                 : "=r"(r0), "=r"(r1), "=r"(r2), "=r"(r3) : "r"(addr));
}

// ---------------- fused prep ----------------
__device__ __forceinline__ void cvt_dev(const float* __restrict__ in,
                                        __half* __restrict__ out,
                                        int R, int Kin, int Kout, int blk) {
    int idx = blk * 256 + threadIdx.x;
    int k8n = Kout >> 3;
    if (idx >= R * k8n) return;
    int r = idx / k8n, k8 = (idx % k8n) << 3;
    __half h[8];
    if (k8 + 8 <= Kin) {
        const float4* p = (const float4*)(in + (size_t)r * Kin + k8);
        float4 v0 = p[0], v1 = p[1];
        h[0] = __float2half_rn(v0.x); h[1] = __float2half_rn(v0.y);
        h[2] = __float2half_rn(v0.z); h[3] = __float2half_rn(v0.w);
        h[4] = __float2half_rn(v1.x); h[5] = __float2half_rn(v1.y);
        h[6] = __float2half_rn(v1.z); h[7] = __float2half_rn(v1.w);
    } else {
        #pragma unroll
        for (int j = 0; j < 8; j++)
            h[j] = (k8 + j < Kin) ? __float2half_rn(in[(size_t)r * Kin + k8 + j]) : __half(0.f);
    }
    uint4 u;
    u.x = *(unsigned*)&h[0]; u.y = *(unsigned*)&h[2];
    u.z = *(unsigned*)&h[4]; u.w = *(unsigned*)&h[6];
    *(uint4*)(out + (size_t)r * Kout + k8) = u;
}

__device__ __forceinline__ void rownorm_dev(const float* __restrict__ in,
                                            float* __restrict__ out,
                                            int M, int K, int blk) {
    int row = blk * 8 + (threadIdx.x >> 5);
    int lane = threadIdx.x & 31;
    if (row >= M) return;
    const float4* p = (const float4*)(in + (size_t)row * K);
    int n4 = K >> 2;
    float s = 0.f;
    for (int i = lane; i < n4; i += 32) {
        float4 v = p[i];
        s += v.x * v.x + v.y * v.y + v.z * v.z + v.w * v.w;
    }
    #pragma unroll
    for (int o = 16; o; o >>= 1) s += __shfl_xor_sync(0xffffffffu, s, o);
    if (lane == 0) out[row] = s;
}

// block ranges
#define NB_CW   1152   // cw  (3072 x 768)
#define NB_W4   1152   // w4  (768 x 3072)
#define NB_TW   48     // tw  (384 x 196 -> 256)
#define NB_W2   37     // w2  (196 x 384)
#define NB_RTW  48     // rownorm tw
#define NB_RCW  384    // rownorm cw
#define NB_Z    48     // zero xn1 + scales
#define NB_Z2   13     // zero xn2 (float4: 3136 stores needed, 13*256=3328)
#define NB_PREP (NB_CW + NB_W4 + NB_TW + NB_W2 + NB_RTW + NB_RCW + NB_Z + NB_Z2)

__global__ void prep_mega(const float* __restrict__ tw, const float* __restrict__ w2,
                          const float* __restrict__ cw, const float* __restrict__ w4,
                          __half* __restrict__ tw16, __half* __restrict__ w216,
                          __half* __restrict__ cw16, __half* __restrict__ w416,
                          float* __restrict__ twn, float* __restrict__ cwn,
                          float* __restrict__ xn1, float* __restrict__ xn2,
                          const float* __restrict__ ta, const float* __restrict__ ca,
                          float* __restrict__ scl) {
    int b = blockIdx.x;
    if (b < NB_CW) { cvt_dev(cw, cw16, CM_, C_, C_, b); return; }
    b -= NB_CW;
    if (b < NB_W4) { cvt_dev(w4, w416, C_, CM_, CM_, b); return; }
    b -= NB_W4;
    if (b < NB_TW) { cvt_dev(tw, tw16, TM_, P_, PPAD, b); return; }
    b -= NB_TW;
    if (b < NB_W2) { cvt_dev(w2, w216, P_, TM_, TM_, b); return; }
    b -= NB_W2;
    if (b < NB_RTW) { rownorm_dev(tw, twn, TM_, P_, b); return; }
    b -= NB_RTW;
    if (b < NB_RCW) { rownorm_dev(cw, cwn, CM_, C_, b); return; }
    b -= NB_RCW;
    if (b < NB_Z) {
        int i = b * 256 + threadIdx.x;
        if (i < B_ * C_ / 4) ((float4*)xn1)[i] = make_float4(0.f, 0.f, 0.f, 0.f);
        if (b == 0 && threadIdx.x == 0) {
            float bt = (float)((double)TM_ / log((double)TM_ + 1.0));
            float bc = (float)((double)CM_ / log((double)CM_ + 1.0));
            scl[0] = powf(sqrtf(bt), ta[0]);
            scl[1] = powf(sqrtf(bc), ca[0]);
        }
        return;
    }
    b -= NB_Z;
    int i = b * 256 + threadIdx.x;
    if (i < B_ * P_ / 4) ((float4*)xn2)[i] = make_float4(0.f, 0.f, 0.f, 0.f);
}

// transpose + convert + fused x-norm partials
__global__ void transpose_cvt_x(const float* __restrict__ x, __half* __restrict__ out,
                                float* __restrict__ xn1) {
    __shared__ float tile[32][33];
    const int b  = blockIdx.z;
    const int c0 = blockIdx.x * 32;
    const int p0 = blockIdx.y * 32;
    const int tx = threadIdx.x, ty = threadIdx.y;
    #pragma unroll
    for (int i = 0; i < 32; i += 8) {
        int p = p0 + ty + i;
        tile[ty + i][tx] = (p < P_) ? x[(size_t)b * P_ * C_ + (size_t)p * C_ + c0 + tx] : 0.f;
    }
    __syncthreads();
    const int tid = ty * 32 + tx;
    const int pl  = (tid & 15) * 2;
    const int ci  = tid >> 4;
    #pragma unroll
    for (int pass = 0; pass < 2; pass++) {
        int cl = pass * 16 + ci;
        __half2 v = __floats2half2_rn(tile[pl][cl], tile[pl + 1][cl]);
        *(__half2*)(out + ((size_t)b * C_ + c0 + cl) * PPAD + p0 + pl) = v;
    }
    if (tid < 32) {
        float s = 0.f;
        #pragma unroll 8
        for (int p = 0; p < 32; p++) { float v = tile[p][tid]; s += v * v; }
        atomicAdd(&xn1[(size_t)b * C_ + c0 + tid], s);
    }
}

// ========== fp16 GEMM: 128x128 block, 32x64 warp tile, BK=64, ldmatrix ==========
#define EPI_YAT16 0
#define EPI_RESD  1
#define EPI_RES32 2

__device__ __forceinline__ void mma_f16(float* c, const unsigned* a, const unsigned* b) {
    asm volatile(
        "mma.sync.aligned.m16n8k16.row.col.f32.f16.f16.f32 "
        "{%0,%1,%2,%3}, {%4,%5,%6,%7}, {%8,%9}, {%0,%1,%2,%3};\n"
        : "+f"(c[0]), "+f"(c[1]), "+f"(c[2]), "+f"(c[3])
        : "r"(a[0]), "r"(a[1]), "r"(a[2]), "r"(a[3]), "r"(b[0]), "r"(b[1]));
}

#define GSMEM_BYTES (3 * (128 * 128 + 128 * 128))   // 98304

template <int EPI>
__global__ __launch_bounds__(256, 2)
void gemm16c(const __half* __restrict__ A, int lda,
             const __half* __restrict__ Bw, int ldb, int NbValid,
             void* __restrict__ OutP, __half* __restrict__ Out16,
             int M, int N, int K, int Mvalid,
             size_t zB, size_t zO,
             const float* __restrict__ bias,
             const float* __restrict__ wn, const float* __restrict__ xn,
             const float* __restrict__ scales, int scale_idx,
             const float* __restrict__ shortcut) {
    constexpr int BM = 128, BN = 128, BK = 64;
    constexpr int ABYTES = BM * 128, BBYTES = BN * 128, STAGE = ABYTES + BBYTES;
    extern __shared__ __align__(128) char smem[];
    const uint32_t sb = smem_u32(smem);

    const int t    = threadIdx.x;
    const int lane = t & 31;
    const int wid  = t >> 5;
    const int warp_m = wid & 3;
    const int warp_n = wid >> 2;
    const int g  = lane >> 2;
    const int tg = lane & 3;

    const size_t zz = blockIdx.z;
    const __half* Bz = Bw + zz * zB;

    const int r0 = blockIdx.y * BM;
    const int n0 = blockIdx.x * BN;
    const int ntiles = K / BK;

    float acc[2][8][4];
    #pragma unroll
    for (int mt = 0; mt < 2; mt++)
        #pragma unroll
        for (int nt = 0; nt < 8; nt++)
            #pragma unroll
            for (int r = 0; r < 4; r++) acc[mt][nt][r] = 0.f;

    auto load_tile = [&](int i, int s) {
        const uint32_t Ab = sb + (uint32_t)s * STAGE;
        const uint32_t Bb = Ab + ABYTES;
        const int k0 = i * BK;
        #pragma unroll
        for (int j = 0; j < 4; j++) {
            int ch = t + j * 256;
            int r = ch >> 3, kq = ch & 7;
            cp16(Ab + (uint32_t)(r * 128 + ((kq ^ (r & 7)) << 4)),
                 A + (size_t)(r0 + r) * lda + k0 + kq * 8, 16);
        }
        #pragma unroll
        for (int j = 0; j < 4; j++) {
            int ch = t + j * 256;
            int r = ch >> 3, kq = ch & 7;
            int nb = (n0 + r < NbValid) ? 16 : 0;
            const __half* src = nb ? (Bz + (size_t)(n0 + r) * ldb + k0 + kq * 8) : Bz;
            cp16(Bb + (uint32_t)(r * 128 + ((kq ^ (r & 7)) << 4)), src, nb);
        }
        cp_commit();
    };

    load_tile(0, 0); load_tile(1, 1); load_tile(2, 2);

    const int Lr  = lane & 7;
    const int hi8 = (lane >> 3) & 1;
    const int h   = lane >> 4;

    for (int i = 0; i < ntiles; i++) {
        int rem = ntiles - 1 - i; if (rem > 2) rem = 2;
        if (rem == 2) cp_wait2(); else if (rem == 1) cp_wait1(); else cp_wait0();
        __syncthreads();

        const uint32_t Ab = sb + (uint32_t)(i % 3) * STAGE;
        const uint32_t Bb = Ab + ABYTES;
        #pragma unroll
        for (int ks = 0; ks < 4; ks++) {
            const uint32_t qoff = (uint32_t)(((2 * ks + h) ^ Lr) << 4);
            unsigned a[2][4];
            #pragma unroll
            for (int mt = 0; mt < 2; mt++) {
                uint32_t ad = Ab + (uint32_t)((warp_m * 32 + mt * 16 + Lr + hi8 * 8) * 128) + qoff;
                ldsm4(a[mt][0], a[mt][1], a[mt][2], a[mt][3], ad);
            }
            unsigned b[8][2];
            #pragma unroll
            for (int p = 0; p < 4; p++) {
                uint32_t bd = Bb + (uint32_t)((warp_n * 64 + p * 16 + Lr + hi8 * 8) * 128) + qoff;
                unsigned q0, q1, q2, q3;
                ldsm4(q0, q1, q2, q3, bd);
                b[2 * p][0] = q0; b[2 * p + 1][0] = q1;
                b[2 * p][1] = q2; b[2 * p + 1][1] = q3;
            }
            #pragma unroll
            for (int mt = 0; mt < 2; mt++)
                #pragma unroll
                for (int nt = 0; nt < 8; nt++)
                    mma_f16(acc[mt][nt], a[mt], b[nt]);
        }
        __syncthreads();
        if (i + 3 < ntiles) load_tile(i + 3, i % 3);
    }

    // ---- epilogue ----
    const float scale = (EPI == EPI_YAT16) ? scales[scale_idx] : 0.f;
    #pragma unroll
    for (int mt = 0; mt < 2; mt++) {
        #pragma unroll
        for (int half = 0; half < 2; half++) {
            const int row = r0 + warp_m * 32 + mt * 16 + g + half * 8;
            if (EPI == EPI_RESD && row >= Mvalid) continue;
            const float xnr = (EPI == EPI_YAT16) ? xn[row] : 0.f;
            const float br  = (EPI == EPI_RESD) ? bias[row] : 0.f;
            float rsum = 0.f;
            #pragma unroll
            for (int nt = 0; nt < 8; nt++) {
                const int col = n0 + warp_n * 64 + nt * 8 + tg * 2;
                const float d0 = acc[mt][nt][half * 2 + 0];
                const float d1 = acc[mt][nt][half * 2 + 1];
                if (EPI == EPI_YAT16) {
                    float dot0 = d0 + bias[col];
                    float dot1 = d1 + bias[col + 1];
                    float v0 = scale * dot0 * dot0 / (wn[col]     + xnr - 2.f * d0 + EPSY);
                    float v1 = scale * dot1 * dot1 / (wn[col + 1] + xnr - 2.f * d1 + EPSY);
                    *(__half2*)(Out16 + (size_t)row * N + col) = __floats2half2_rn(v0, v1);
                } else if (EPI == EPI_RES32) {
                    float* Out = (float*)OutP;
                    size_t o = (size_t)row * N + col;
                    float2 v = make_float2(shortcut[o] + d0 + bias[col],
                                           shortcut[o + 1] + d1 + bias[col + 1]);
                    *(float2*)(Out + o) = v;
                } else { // EPI_RESD: batched, coalesced dual write + fused rownorm
                    float* Out = (float*)OutP;
                    size_t o = zz * zO + (size_t)row * N + col;
                    float v0 = shortcut[o]     + d0 + br;
                    float v1 = shortcut[o + 1] + d1 + br;
                    *(float2*)(Out + o) = make_float2(v0, v1);
                    *(__half2*)(Out16 + o) = __floats2half2_rn(v0, v1);
                    rsum += v0 * v0 + v1 * v1;
                }
            }
            if (EPI == EPI_RESD)
                atomicAdd((float*)wn + zz * P_ + row, rsum);   // wn carries xn2 out-ptr
        }
    }
}

// ---------------- launch (single stream, serial) ----------------
extern "C" void kernel_launch(void* const* d_in, const int* in_sizes, int n_in,
                              void* d_out, int out_size) {
    const float* x  = (const float*)d_in[0];
    const float* tw = (const float*)d_in[1];
    const float* tb = (const float*)d_in[2];
    const float* ta = (const float*)d_in[3];
    const float* w2 = (const float*)d_in[4];
    const float* b2 = (const float*)d_in[5];
    const float* cw = (const float*)d_in[6];
    const float* cb = (const float*)d_in[7];
    const float* ca = (const float*)d_in[8];
    const float* w4 = (const float*)d_in[9];
    const float* b4 = (const float*)d_in[10];
    float* out = (float*)d_out;

    __half *xt16, *tw16, *w216, *cw16, *w416, *H116, *X116, *H316;
    float *X1, *twn, *cwn, *xn1, *xn2, *scl;
    cudaGetSymbolAddress((void**)&xt16, g_xt16);
    cudaGetSymbolAddress((void**)&tw16, g_tw16);
    cudaGetSymbolAddress((void**)&w216, g_w216);
    cudaGetSymbolAddress((void**)&cw16, g_cw16);
    cudaGetSymbolAddress((void**)&w416, g_w416);
    cudaGetSymbolAddress((void**)&H116, g_H116);
    cudaGetSymbolAddress((void**)&X1,   g_X1);
    cudaGetSymbolAddress((void**)&X116, g_X116);
    cudaGetSymbolAddress((void**)&H316, g_H316);
    cudaGetSymbolAddress((void**)&twn,  g_twn);
    cudaGetSymbolAddress((void**)&cwn,  g_cwn);
    cudaGetSymbolAddress((void**)&xn1,  g_xn1);
    cudaGetSymbolAddress((void**)&xn2,  g_xn2);
    cudaGetSymbolAddress((void**)&scl,  g_scales);

    static int once = 0;
    if (!once) {
        cudaFuncSetAttribute(gemm16c<EPI_YAT16>,
            cudaFuncAttributeMaxDynamicSharedMemorySize, GSMEM_BYTES);
        cudaFuncSetAttribute(gemm16c<EPI_RESD>,
            cudaFuncAttributeMaxDynamicSharedMemorySize, GSMEM_BYTES);
        cudaFuncSetAttribute(gemm16c<EPI_RES32>,
            cudaFuncAttributeMaxDynamicSharedMemorySize, GSMEM_BYTES);
        once = 1;
    }

    const int M1 = B_ * C_;   // 49152
    const int M3 = B_ * P_;   // 12544

    // ---- prep: 1 fused kernel + transpose ----
    prep_mega<<<NB_PREP, 256>>>(tw, w2, cw, w4, tw16, w216, cw16, w416,
                                twn, cwn, xn1, xn2, ta, ca, scl);
    dim3 tb32(32, 8);
    transpose_cvt_x<<<dim3(C_ / 32, PPAD / 32, B_), tb32>>>(x, xt16, xn1);

    // GEMM1 + YAT (token): A=xt16 (M1 x 256), B=tw16 (384 x 256) -> H116 fp16
    gemm16c<EPI_YAT16><<<dim3(TM_ / 128, M1 / 128, 1), 256, GSMEM_BYTES>>>(
        xt16, PPAD, tw16, PPAD, TM_, nullptr, H116,
        M1, TM_, PPAD, M1, 0, 0, tb, twn, xn1, scl, 0, nullptr);

    // GEMM2 (batched over b): X1[b,p,c] = sum_t w2[p,t] * H1[(b,c),t] + x + b2[p]
    // fused xn2 rownorm via atomics (xn2 passed through the wn slot)
    gemm16c<EPI_RESD><<<dim3(C_ / 128, 2, B_), 256, GSMEM_BYTES>>>(
        w216, TM_, H116, TM_, C_, X1, X116,
        P2PAD, C_, TM_, P_, (size_t)C_ * TM_, (size_t)P_ * C_,
        b2, xn2, nullptr, nullptr, 0, x);

    // GEMM3 + YAT (channel): A=X116 (M3 x 768), B=cw16 (3072 x 768) -> H316 fp16
    gemm16c<EPI_YAT16><<<dim3(CM_ / 128, M3 / 128, 1), 256, GSMEM_BYTES>>>(
        X116, C_, cw16, C_, CM_, nullptr, H316,
        M3, CM_, C_, M3, 0, 0, cb, cwn, xn2, scl, 1, nullptr);

    // GEMM4 + residual: A=H316 (M3 x 3072), B=w416 (768 x 3072) -> out fp32
    gemm16c<EPI_RES32><<<dim3(C_ / 128, M3 / 128, 1), 256, GSMEM_BYTES>>>(
        H316, CM_, w416, CM_, C_, out, nullptr,
        M3, C_, CM_, M3, 0, 0, b4, nullptr, nullptr, nullptr, 0, X1);
}